// round 2
// baseline (speedup 1.0000x reference)
#include <cuda_runtime.h>
#include <cstdint>

// Problem constants
#define B_    256
#define T_    512
#define DIN   128
#define DST   128
#define DHID  512
#define MROWS 8      // batch rows per 4-CTA cluster
#define WPAD  132    // padded SMEM row stride (floats): 132%32=4 -> conflict-free float4

// Scratch: U[t][b][n] = x[b,t,:] @ W1[:128,:] + b1   (fp32, 256 MB, __device__ global per rules)
__device__ float g_U[(size_t)T_ * B_ * DHID];

__device__ __forceinline__ float fast_tanh(float x) {
    // tanh(x) = 1 - 2/(exp(2x)+1); __expf/__fdividef accurate to ~1e-6 rel.
    float e = __expf(2.0f * x);
    return 1.0f - __fdividef(2.0f, e + 1.0f);
}

// ---------------- cluster helpers (inline PTX, no cg dependency) ----------------
__device__ __forceinline__ uint32_t smem_u32(const void* p) {
    return (uint32_t)__cvta_generic_to_shared(p);
}
__device__ __forceinline__ uint32_t mapa_shared(uint32_t addr, uint32_t rank) {
    uint32_t r;
    asm("mapa.shared::cluster.u32 %0, %1, %2;" : "=r"(r) : "r"(addr), "r"(rank));
    return r;
}
__device__ __forceinline__ void st_shared_cluster_f32(uint32_t addr, float v) {
    asm volatile("st.shared::cluster.f32 [%0], %1;" :: "r"(addr), "f"(v) : "memory");
}
__device__ __forceinline__ void cluster_sync_all() {
    asm volatile("barrier.cluster.arrive.aligned;" ::: "memory");
    asm volatile("barrier.cluster.wait.aligned;"   ::: "memory");
}
__device__ __forceinline__ uint32_t cluster_rank() {
    uint32_t r; asm("mov.u32 %0, %%cluster_ctarank;" : "=r"(r)); return r;
}

// =====================================================================
// Kernel 1: U = X @ W1x + b1   (fp32 tiled GEMM, time-parallel part)
// Grid: (2048, 4); 256 threads. Tile: 64 rows (b*T+t linear) x 128 cols.
// =====================================================================
__global__ __launch_bounds__(256) void precompute_u(
    const float* __restrict__ X,   // [B, T, DIN] row-major
    const float* __restrict__ W1,  // [DIN+DST, DHID]
    const float* __restrict__ b1)  // [DHID]
{
    extern __shared__ float sm[];
    float* sX = sm;             // 64 x 128
    float* sW = sm + 64 * DIN;  // 128 x 128

    const int tid = threadIdx.x;
    const int rb  = blockIdx.x;   // 64-row block over B*T
    const int nb  = blockIdx.y;   // 128-col block over DHID

    // Load X tile (contiguous 32 KB)
    {
        const float4* Xg = (const float4*)(X + (size_t)rb * 64 * DIN);
        float4* sX4 = (float4*)sX;
        #pragma unroll
        for (int i = tid; i < 64 * DIN / 4; i += 256) sX4[i] = Xg[i];
    }
    // Load W1x slice [k=0..127][c=0..127]
    {
        float4* sW4 = (float4*)sW;
        for (int i = tid; i < 4096; i += 256) {
            int k = i >> 5, c4 = i & 31;
            sW4[i] = *(const float4*)(W1 + (size_t)k * DHID + nb * 128 + c4 * 4);
        }
    }
    __syncthreads();

    const int lane = tid & 31, wrp = tid >> 5;
    const int c0 = lane * 4, m0 = wrp * 8;

    float acc[8][4];
    #pragma unroll
    for (int m = 0; m < 8; ++m)
        #pragma unroll
        for (int c = 0; c < 4; ++c) acc[m][c] = 0.0f;

    const float4* sW4 = (const float4*)sW;
    #pragma unroll 4
    for (int k4 = 0; k4 < 32; ++k4) {
        float4 xv[8];
        #pragma unroll
        for (int m = 0; m < 8; ++m)
            xv[m] = ((const float4*)(sX + (m0 + m) * DIN))[k4];  // warp-broadcast
        #pragma unroll
        for (int kk = 0; kk < 4; ++kk) {
            float4 wv = sW4[(k4 * 4 + kk) * 32 + lane];          // conflict-free
            #pragma unroll
            for (int m = 0; m < 8; ++m) {
                float xs = (kk == 0) ? xv[m].x : (kk == 1) ? xv[m].y
                         : (kk == 2) ? xv[m].z : xv[m].w;
                acc[m][0] = fmaf(xs, wv.x, acc[m][0]);
                acc[m][1] = fmaf(xs, wv.y, acc[m][1]);
                acc[m][2] = fmaf(xs, wv.z, acc[m][2]);
                acc[m][3] = fmaf(xs, wv.w, acc[m][3]);
            }
        }
    }

    float4 bv = *(const float4*)(b1 + nb * 128 + c0);
    #pragma unroll
    for (int m = 0; m < 8; ++m) {
        int row_in = rb * 64 + m0 + m;           // linear b*T + t
        int b = row_in >> 9;                     // / T_
        int t = row_in & (T_ - 1);
        float4 o;
        o.x = acc[m][0] + bv.x; o.y = acc[m][1] + bv.y;
        o.z = acc[m][2] + bv.z; o.w = acc[m][3] + bv.w;
        *(float4*)(g_U + ((size_t)t * B_ + b) * DHID + nb * 128 + c0) = o;
    }
}

// =====================================================================
// Kernel 2: persistent recurrence. 32 clusters of 4 CTAs, M=8 rows/cluster.
// CTA j of a cluster owns DHID columns [128j,128j+128) of W1a and the
// matching 128 rows of W2 (fp32 in SMEM). Per step:
//   h_j = tanh(U_slice + a @ W1a_j)        [8 x 128]
//   s_j = h_j @ W2_j                       [8 x 128] partial over k
//   scatter s_j quarters to owner CTAs (DSMEM), cluster sync,
//   owner reduces + adds b2, broadcasts new a quarter to all CTAs, sync.
// =====================================================================
__global__ __launch_bounds__(128) __cluster_dims__(4, 1, 1)
void rnn_recur(const float* __restrict__ a0,
               const float* __restrict__ W1,
               const float* __restrict__ W2,
               const float* __restrict__ b2,
               float* __restrict__ out)
{
    extern __shared__ float sm[];
    float* sW1T = sm;                       // 128 x WPAD  (W1a slice, [n][k])
    float* sW2T = sW1T + 128 * WPAD;        // 128 x WPAD  (W2 slice,  [n2][k])
    float* sA   = sW2T + 128 * WPAD;        // 8 x 128     (full current a)
    float* sH   = sA + MROWS * DST;         // 8 x 128     (h slice, [m][klocal])
    float* sRed = sH + MROWS * DST;         // 4 x 8 x 32  (partials for my quarter)
    float* sB2  = sRed + 4 * MROWS * 32;    // 32

    const int j   = (int)cluster_rank();    // 0..3
    const int g   = blockIdx.x >> 2;        // cluster index = batch-row group
    const int tid = threadIdx.x;
    const int nt  = tid;                    // column within my slice / state col

    // ---- one-time loads ----
    for (int i = tid; i < 128 * 128; i += 128) {
        int n = i & 127, k = i >> 7;
        sW1T[n * WPAD + k] = W1[(size_t)(DIN + k) * DHID + j * 128 + n];
        sW2T[n * WPAD + k] = W2[(size_t)(j * 128 + k) * DST + n];
    }
    for (int i = tid; i < MROWS * DST; i += 128)
        sA[i] = a0[(size_t)g * MROWS * DST + i];
    if (tid < 32) sB2[tid] = b2[j * 32 + tid];
    cluster_sync_all();

    // DSMEM addresses (fixed per thread)
    const int q  = nt >> 5;        // quarter owner of my output column
    const int ln = nt & 31;
    const uint32_t sRed_u = smem_u32(sRed);
    const uint32_t sA_u   = smem_u32(sA);
    const uint32_t redDst = mapa_shared(sRed_u, (uint32_t)q) + (uint32_t)((j * MROWS * 32 + ln) * 4);
    uint32_t aRem[4];
    #pragma unroll
    for (int c = 0; c < 4; ++c) aRem[c] = mapa_shared(sA_u, (uint32_t)c);

    // U prefetch for t=0
    float uPref[MROWS];
    {
        int base = (g * MROWS) * DHID + j * 128 + nt;   // t = 0
        #pragma unroll
        for (int m = 0; m < MROWS; ++m) uPref[m] = g_U[base + m * DHID];
    }

    const float4* w1row = (const float4*)(sW1T + nt * WPAD);
    const float4* w2row = (const float4*)(sW2T + nt * WPAD);

    for (int t = 0; t < T_; ++t) {
        // z accumulators seeded with U (contains b1)
        float acc[MROWS];
        #pragma unroll
        for (int m = 0; m < MROWS; ++m) acc[m] = uPref[m];

        // prefetch next step's U (hidden under GEMM1)
        if (t + 1 < T_) {
            int base = ((t + 1) * B_ + g * MROWS) * DHID + j * 128 + nt;
            #pragma unroll
            for (int m = 0; m < MROWS; ++m) uPref[m] = g_U[base + m * DHID];
        }

        // ---- GEMM1: acc[m] += sum_k a[m,k] * W1a[k, my col] ----
        #pragma unroll 4
        for (int k4 = 0; k4 < 32; ++k4) {
            float4 w = w1row[k4];
            #pragma unroll
            for (int m = 0; m < MROWS; ++m) {
                float4 av = ((const float4*)(sA + m * DST))[k4];  // broadcast
                acc[m] = fmaf(av.x, w.x, acc[m]);
                acc[m] = fmaf(av.y, w.y, acc[m]);
                acc[m] = fmaf(av.z, w.z, acc[m]);
                acc[m] = fmaf(av.w, w.w, acc[m]);
            }
        }

        // ---- tanh, stage h slice [m][klocal=nt] ----
        #pragma unroll
        for (int m = 0; m < MROWS; ++m)
            sH[m * 128 + nt] = fast_tanh(acc[m]);
        __syncthreads();

        // ---- GEMM2: s[m] = sum_klocal h[m,klocal] * W2[klocal, my state col] ----
        float s[MROWS];
        #pragma unroll
        for (int m = 0; m < MROWS; ++m) s[m] = 0.0f;
        #pragma unroll 4
        for (int k4 = 0; k4 < 32; ++k4) {
            float4 w = w2row[k4];
            #pragma unroll
            for (int m = 0; m < MROWS; ++m) {
                float4 hv = ((const float4*)(sH + m * 128))[k4];  // broadcast
                s[m] = fmaf(hv.x, w.x, s[m]);
                s[m] = fmaf(hv.y, w.y, s[m]);
                s[m] = fmaf(hv.z, w.z, s[m]);
                s[m] = fmaf(hv.w, w.w, s[m]);
            }
        }

        // ---- scatter partials to quarter-owner CTA (DSMEM) ----
        #pragma unroll
        for (int m = 0; m < MROWS; ++m)
            st_shared_cluster_f32(redDst + (uint32_t)(m * 32 * 4), s[m]);
        cluster_sync_all();

        // ---- owner reduces its quarter, updates a everywhere ----
        #pragma unroll
        for (int rep = 0; rep < 2; ++rep) {
            int item = tid + rep * 128;        // 0..255 = 8m x 32n
            int m = item >> 5, n = item & 31;
            float v = sA[m * DST + j * 32 + n] + sB2[n];
            #pragma unroll
            for (int c = 0; c < 4; ++c) v += sRed[(c * MROWS + m) * 32 + n];
            #pragma unroll
            for (int c = 0; c < 4; ++c)
                st_shared_cluster_f32(aRem[c] + (uint32_t)((m * DST + j * 32 + n) * 4), v);
        }
        cluster_sync_all();
    }

    // ---- output: CTA j writes its quarter of its 8 rows ----
    #pragma unroll
    for (int rep = 0; rep < 2; ++rep) {
        int item = tid + rep * 128;
        int m = item >> 5, n = item & 31;
        out[(size_t)(g * MROWS + m) * DST + j * 32 + n] = sA[m * DST + j * 32 + n];
    }
}

// =====================================================================
extern "C" void kernel_launch(void* const* d_in, const int* in_sizes, int n_in,
                              void* d_out, int out_size)
{
    const float* X  = (const float*)d_in[0];  // inputs [B,T,DIN]
    const float* a0 = (const float*)d_in[1];  // [B,DST]
    const float* W1 = (const float*)d_in[2];  // [DIN+DST, DHID]
    const float* b1 = (const float*)d_in[3];  // [DHID]
    const float* W2 = (const float*)d_in[4];  // [DHID, DST]
    const float* b2 = (const float*)d_in[5];  // [DST]
    float* out = (float*)d_out;

    constexpr int PRE_SMEM = (64 * DIN + 128 * 128) * 4;                     // 96 KB
    constexpr int REC_SMEM = (2 * 128 * WPAD + 2 * MROWS * DST + 4 * MROWS * 32 + 32) * 4; // 147584 B

    cudaFuncSetAttribute(precompute_u, cudaFuncAttributeMaxDynamicSharedMemorySize, PRE_SMEM);
    cudaFuncSetAttribute(rnn_recur,    cudaFuncAttributeMaxDynamicSharedMemorySize, REC_SMEM);

    // Phase 1: time-parallel U = X @ W1x + b1
    precompute_u<<<dim3((B_ * T_) / 64, DHID / 128), 256, PRE_SMEM>>>(X, W1, b1);
    // Phase 2: persistent sequential recurrence (32 clusters x 4 CTAs)
    rnn_recur<<<(B_ / MROWS) * 4, 128, REC_SMEM>>>(a0, W1, W2, b2, out);
}

// round 5
// speedup vs baseline: 1.1825x; 1.1825x over previous
#include <cuda_runtime.h>
#include <cstdint>

// Problem constants
#define B_    256
#define T_    512
#define DIN   128
#define DST   128
#define DHID  512
#define MROWS 8      // batch rows per 4-CTA cluster
#define WPAD  132    // padded SMEM row stride (floats)

// Scratch: U[t][b][n] = x[b,t,:] @ W1[:128,:] + b1   (fp32)
__device__ float g_U[(size_t)T_ * B_ * DHID];

__device__ __forceinline__ float fast_tanh(float x) {
    float e = __expf(2.0f * x);
    return 1.0f - __fdividef(2.0f, e + 1.0f);
}

// ---------------- PTX helpers ----------------
__device__ __forceinline__ uint32_t smem_u32(const void* p) {
    return (uint32_t)__cvta_generic_to_shared(p);
}
__device__ __forceinline__ uint32_t mapa_shared(uint32_t addr, uint32_t rank) {
    uint32_t r;
    asm("mapa.shared::cluster.u32 %0, %1, %2;" : "=r"(r) : "r"(addr), "r"(rank));
    return r;
}
__device__ __forceinline__ void cluster_sync_all() {
    asm volatile("barrier.cluster.arrive.aligned;" ::: "memory");
    asm volatile("barrier.cluster.wait.aligned;"   ::: "memory");
}
__device__ __forceinline__ uint32_t cluster_rank() {
    uint32_t r; asm("mov.u32 %0, %%cluster_ctarank;" : "=r"(r)); return r;
}
// packed fp32x2 FMA (two independent fp32 lanes per 64-bit reg)
__device__ __forceinline__ uint64_t fma2(uint64_t a, uint64_t b, uint64_t c) {
    uint64_t d;
    asm("fma.rn.f32x2 %0, %1, %2, %3;" : "=l"(d) : "l"(a), "l"(b), "l"(c));
    return d;
}
__device__ __forceinline__ float hsum2(uint64_t v) {
    return __uint_as_float((uint32_t)v) + __uint_as_float((uint32_t)(v >> 32));
}
// st.async: remote SMEM store counted on the destination CTA's mbarrier
__device__ __forceinline__ void st_async_f32(uint32_t addr, float v, uint32_t mbar) {
    asm volatile(
        "st.async.shared::cluster.mbarrier::complete_tx::bytes.u32 [%0], %1, [%2];"
        :: "r"(addr), "r"(__float_as_uint(v)), "r"(mbar) : "memory");
}
__device__ __forceinline__ void mbar_init(uint32_t mbar, uint32_t count) {
    asm volatile("mbarrier.init.shared.b64 [%0], %1;" :: "r"(mbar), "r"(count) : "memory");
}
__device__ __forceinline__ void mbar_expect_tx(uint32_t mbar, uint32_t bytes) {
    asm volatile("mbarrier.arrive.expect_tx.shared.b64 _, [%0], %1;"
                 :: "r"(mbar), "r"(bytes) : "memory");
}
// cluster-scope acquire: writers are peer CTAs (st.async)
__device__ __forceinline__ void mbar_wait(uint32_t mbar, uint32_t parity) {
    uint32_t done;
    asm volatile(
        "{\n\t.reg .pred p;\n\t"
        "mbarrier.try_wait.parity.acquire.cluster.shared::cta.b64 p, [%1], %2;\n\t"
        "selp.b32 %0, 1, 0, p;\n\t}"
        : "=r"(done) : "r"(mbar), "r"(parity) : "memory");
    if (!done) {
        asm volatile(
            "{\n\t.reg .pred P1;\n\t"
            "WAIT_LOOP_%=:\n\t"
            "mbarrier.try_wait.parity.acquire.cluster.shared::cta.b64 P1, [%0], %1, 0x989680;\n\t"
            "@P1 bra.uni WAIT_DONE_%=;\n\t"
            "bra.uni WAIT_LOOP_%=;\n\t"
            "WAIT_DONE_%=:\n\t}"
            :: "r"(mbar), "r"(parity) : "memory");
    }
}

// =====================================================================
// Kernel 1: U = X @ W1x + b1  (time-parallel part; known-good from R2)
// =====================================================================
__global__ __launch_bounds__(256) void precompute_u(
    const float* __restrict__ X, const float* __restrict__ W1,
    const float* __restrict__ b1)
{
    extern __shared__ float sm[];
    float* sX = sm;             // 64 x 128
    float* sW = sm + 64 * DIN;  // 128 x 128

    const int tid = threadIdx.x;
    const int rb  = blockIdx.x;
    const int nb  = blockIdx.y;

    {
        const float4* Xg = (const float4*)(X + (size_t)rb * 64 * DIN);
        float4* sX4 = (float4*)sX;
        #pragma unroll
        for (int i = tid; i < 64 * DIN / 4; i += 256) sX4[i] = Xg[i];
    }
    {
        float4* sW4 = (float4*)sW;
        for (int i = tid; i < 4096; i += 256) {
            int k = i >> 5, c4 = i & 31;
            sW4[i] = *(const float4*)(W1 + (size_t)k * DHID + nb * 128 + c4 * 4);
        }
    }
    __syncthreads();

    const int lane = tid & 31, wrp = tid >> 5;
    const int c0 = lane * 4, m0 = wrp * 8;

    float acc[8][4];
    #pragma unroll
    for (int m = 0; m < 8; ++m)
        #pragma unroll
        for (int c = 0; c < 4; ++c) acc[m][c] = 0.0f;

    const float4* sW4 = (const float4*)sW;
    #pragma unroll 4
    for (int k4 = 0; k4 < 32; ++k4) {
        float4 xv[8];
        #pragma unroll
        for (int m = 0; m < 8; ++m)
            xv[m] = ((const float4*)(sX + (m0 + m) * DIN))[k4];
        #pragma unroll
        for (int kk = 0; kk < 4; ++kk) {
            float4 wv = sW4[(k4 * 4 + kk) * 32 + lane];
            #pragma unroll
            for (int m = 0; m < 8; ++m) {
                float xs = (kk == 0) ? xv[m].x : (kk == 1) ? xv[m].y
                         : (kk == 2) ? xv[m].z : xv[m].w;
                acc[m][0] = fmaf(xs, wv.x, acc[m][0]);
                acc[m][1] = fmaf(xs, wv.y, acc[m][1]);
                acc[m][2] = fmaf(xs, wv.z, acc[m][2]);
                acc[m][3] = fmaf(xs, wv.w, acc[m][3]);
            }
        }
    }

    float4 bv = *(const float4*)(b1 + nb * 128 + c0);
    #pragma unroll
    for (int m = 0; m < 8; ++m) {
        int row_in = rb * 64 + m0 + m;
        int b = row_in >> 9;
        int t = row_in & (T_ - 1);
        float4 o;
        o.x = acc[m][0] + bv.x; o.y = acc[m][1] + bv.y;
        o.z = acc[m][2] + bv.z; o.w = acc[m][3] + bv.w;
        *(float4*)(g_U + ((size_t)t * B_ + b) * DHID + nb * 128 + c0) = o;
    }
}

// =====================================================================
// Kernel 2: persistent recurrence. 32 clusters x 4 CTAs, 256 thr/CTA.
// Thread (half, nt): column nt of this CTA's DHID slice, rows half*4..+3.
// Packed f32x2 FMA; st.async + tx-counted mbarrier phases (no in-loop
// cluster.sync).
// =====================================================================
__global__ __launch_bounds__(256) __cluster_dims__(4, 1, 1)
void rnn_recur(const float* __restrict__ a0,
               const float* __restrict__ W1,
               const float* __restrict__ W2,
               const float* __restrict__ b2,
               float* __restrict__ out)
{
    extern __shared__ float sm[];
    // sm[0..3]: two mbarriers (16B)
    float* sW1T = sm + 4;                   // 128 x WPAD
    float* sW2T = sW1T + 128 * WPAD;        // 128 x WPAD
    float* sA   = sW2T + 128 * WPAD;        // 8 x 128
    float* sH   = sA + MROWS * DST;         // 8 x 128
    float* sRed = sH + MROWS * DST;         // 4 src CTAs x 8 x 32
    float* sB2  = sRed + 4 * MROWS * 32;    // 32

    const uint32_t mbRed = smem_u32(sm);      // scatter-complete barrier
    const uint32_t mbA   = smem_u32(sm) + 8;  // broadcast-complete barrier

    const int j    = (int)cluster_rank();   // 0..3
    const int g    = blockIdx.x >> 2;       // batch-row group
    const int tid  = threadIdx.x;
    const int nt   = tid & 127;             // my column in slice
    const int half = tid >> 7;              // row half (0/1)
    const int m0   = half * 4;

    // ---- one-time loads ----
    for (int i = tid; i < 128 * 128; i += 256) {
        int n = i & 127, k = i >> 7;
        sW1T[n * WPAD + k] = W1[(size_t)(DIN + k) * DHID + j * 128 + n];
        sW2T[n * WPAD + k] = W2[(size_t)(j * 128 + k) * DST + n];
    }
    for (int i = tid; i < MROWS * DST; i += 256)
        sA[i] = a0[(size_t)g * MROWS * DST + i];
    if (tid < 32) sB2[tid] = b2[j * 32 + tid];
    if (tid == 0) { mbar_init(mbRed, 1); mbar_init(mbA, 1); }
    cluster_sync_all();   // weights + a0 + mbarriers visible cluster-wide

    // ---- fixed DSMEM addresses ----
    const int q  = nt >> 5;          // owner CTA of my output column
    const int ln = nt & 31;
    const uint32_t sRed_u = smem_u32(sRed);
    const uint32_t sA_u   = smem_u32(sA);
    // scatter: rows m0..m0+3 of column nt -> owner q
    const uint32_t redDst   = mapa_shared(sRed_u, (uint32_t)q)
                            + (uint32_t)(((j * MROWS + m0) * 32 + ln) * 4);
    const uint32_t mbRedRem = mapa_shared(mbRed, (uint32_t)q);
    // broadcast: my reduce item (rm, rn) -> all 4 CTAs
    const int rm = tid >> 5, rn = tid & 31;
    uint32_t aRem[4], mbARem[4];
    #pragma unroll
    for (int c = 0; c < 4; ++c) {
        aRem[c]  = mapa_shared(sA_u, (uint32_t)c)
                 + (uint32_t)((rm * DST + j * 32 + rn) * 4);
        mbARem[c] = mapa_shared(mbA, (uint32_t)c);
    }

    // U prefetch for t=0 (my 4 rows)
    float uPref[4];
    {
        size_t base = (size_t)(g * MROWS + m0) * DHID + j * 128 + nt;
        #pragma unroll
        for (int m = 0; m < 4; ++m) uPref[m] = g_U[base + (size_t)m * DHID];
    }

    const ulonglong2* w1row = (const ulonglong2*)(sW1T + nt * WPAD);
    const ulonglong2* w2row = (const ulonglong2*)(sW2T + nt * WPAD);
    const ulonglong2* sA2   = (const ulonglong2*)sA;
    const ulonglong2* sH2   = (const ulonglong2*)sH;

    for (int t = 0; t < T_; ++t) {
        const uint32_t par = (uint32_t)(t & 1);
        if (tid == 0) { mbar_expect_tx(mbRed, 4096); mbar_expect_tx(mbA, 4096); }

        // prefetch next U (hidden under GEMM1)
        float uNext[4] = {0.f, 0.f, 0.f, 0.f};
        if (t + 1 < T_) {
            size_t base = ((size_t)(t + 1) * B_ + g * MROWS + m0) * DHID + j * 128 + nt;
            #pragma unroll
            for (int m = 0; m < 4; ++m) uNext[m] = g_U[base + (size_t)m * DHID];
        }

        // ---- GEMM1 (packed): z[m] = U + sum_k a[m,k]*W1a[k,nt] ----
        uint64_t acc[4] = {0ull, 0ull, 0ull, 0ull};
        #pragma unroll 8
        for (int k4 = 0; k4 < 32; ++k4) {
            ulonglong2 w = w1row[k4];
            #pragma unroll
            for (int m = 0; m < 4; ++m) {
                ulonglong2 av = sA2[(m0 + m) * 32 + k4];   // broadcast
                acc[m] = fma2(av.x, w.x, acc[m]);
                acc[m] = fma2(av.y, w.y, acc[m]);
            }
        }

        // ---- tanh, stage h slice ----
        #pragma unroll
        for (int m = 0; m < 4; ++m)
            sH[(m0 + m) * 128 + nt] = fast_tanh(hsum2(acc[m]) + uPref[m]);
        #pragma unroll
        for (int m = 0; m < 4; ++m) uPref[m] = uNext[m];
        __syncthreads();

        // ---- GEMM2 (packed): s[m] = sum_k h[m,k]*W2[k,nt] ----
        uint64_t s2[4] = {0ull, 0ull, 0ull, 0ull};
        #pragma unroll 8
        for (int k4 = 0; k4 < 32; ++k4) {
            ulonglong2 w = w2row[k4];
            #pragma unroll
            for (int m = 0; m < 4; ++m) {
                ulonglong2 hv = sH2[(m0 + m) * 32 + k4];   // broadcast
                s2[m] = fma2(hv.x, w.x, s2[m]);
                s2[m] = fma2(hv.y, w.y, s2[m]);
            }
        }

        // ---- scatter partials to owner CTA (st.async -> owner's mbRed) ----
        #pragma unroll
        for (int m = 0; m < 4; ++m)
            st_async_f32(redDst + (uint32_t)(m * 32 * 4), hsum2(s2[m]), mbRedRem);

        // wait: all 4 KB of partials for my quarter arrived
        mbar_wait(mbRed, par);

        // ---- reduce my item, broadcast new a to all CTAs (-> their mbA) ----
        {
            float v = sA[rm * DST + j * 32 + rn] + sB2[rn];
            #pragma unroll
            for (int c = 0; c < 4; ++c) v += sRed[(c * MROWS + rm) * 32 + rn];
            #pragma unroll
            for (int c = 0; c < 4; ++c) st_async_f32(aRem[c], v, mbARem[c]);
        }

        // wait: full new a (4 KB from 4 owners) arrived
        mbar_wait(mbA, par);
        __syncthreads();   // all threads past the wait before anyone reads sA
    }

    // ---- output: my reduce item ----
    out[(size_t)(g * MROWS + rm) * DST + j * 32 + rn] = sA[rm * DST + j * 32 + rn];
}

// =====================================================================
extern "C" void kernel_launch(void* const* d_in, const int* in_sizes, int n_in,
                              void* d_out, int out_size)
{
    const float* X  = (const float*)d_in[0];
    const float* a0 = (const float*)d_in[1];
    const float* W1 = (const float*)d_in[2];
    const float* b1 = (const float*)d_in[3];
    const float* W2 = (const float*)d_in[4];
    const float* b2 = (const float*)d_in[5];
    float* out = (float*)d_out;

    constexpr int PRE_SMEM = (64 * DIN + 128 * 128) * 4;
    constexpr int REC_SMEM = (4 + 2 * 128 * WPAD + 2 * MROWS * DST
                              + 4 * MROWS * 32 + 32) * 4;

    cudaFuncSetAttribute(precompute_u, cudaFuncAttributeMaxDynamicSharedMemorySize, PRE_SMEM);
    cudaFuncSetAttribute(rnn_recur,    cudaFuncAttributeMaxDynamicSharedMemorySize, REC_SMEM);

    precompute_u<<<dim3((B_ * T_) / 64, DHID / 128), 256, PRE_SMEM>>>(X, W1, b1);
    rnn_recur<<<(B_ / MROWS) * 4, 256, REC_SMEM>>>(a0, W1, W2, b2, out);
}

// round 16
// speedup vs baseline: 1.6576x; 1.4018x over previous
#include <cuda_runtime.h>
#include <cstdint>

// Problem constants
#define B_    256
#define T_    512
#define DIN   128
#define DST   128
#define DHID  512
#define MROWS 8      // batch rows per 4-CTA cluster

// Scratch: U[t][b][n] = x[b,t,:] @ W1[:128,:] + b1   (fp32)
__device__ float g_U[(size_t)T_ * B_ * DHID];

__device__ __forceinline__ float fast_tanh(float x) {
    float e = __expf(2.0f * x);
    return 1.0f - __fdividef(2.0f, e + 1.0f);
}

// ---------------- PTX helpers ----------------
__device__ __forceinline__ uint32_t smem_u32(const void* p) {
    return (uint32_t)__cvta_generic_to_shared(p);
}
__device__ __forceinline__ uint32_t mapa_shared(uint32_t addr, uint32_t rank) {
    uint32_t r;
    asm("mapa.shared::cluster.u32 %0, %1, %2;" : "=r"(r) : "r"(addr), "r"(rank));
    return r;
}
__device__ __forceinline__ void cluster_sync_all() {
    asm volatile("barrier.cluster.arrive.aligned;" ::: "memory");
    asm volatile("barrier.cluster.wait.aligned;"   ::: "memory");
}
__device__ __forceinline__ uint32_t cluster_rank() {
    uint32_t r; asm("mov.u32 %0, %%cluster_ctarank;" : "=r"(r)); return r;
}
// packed fp32x2 FMA (two independent fp32 lanes per 64-bit reg)
__device__ __forceinline__ uint64_t fma2(uint64_t a, uint64_t b, uint64_t c) {
    uint64_t d;
    asm("fma.rn.f32x2 %0, %1, %2, %3;" : "=l"(d) : "l"(a), "l"(b), "l"(c));
    return d;
}
__device__ __forceinline__ float hsum2(uint64_t v) {
    return __uint_as_float((uint32_t)v) + __uint_as_float((uint32_t)(v >> 32));
}
__device__ __forceinline__ uint64_t pack2(float lo, float hi) {
    return (uint64_t)__float_as_uint(lo) | ((uint64_t)__float_as_uint(hi) << 32);
}
// st.async: remote SMEM store counted on the destination CTA's mbarrier
__device__ __forceinline__ void st_async_f32(uint32_t addr, float v, uint32_t mbar) {
    asm volatile(
        "st.async.shared::cluster.mbarrier::complete_tx::bytes.u32 [%0], %1, [%2];"
        :: "r"(addr), "r"(__float_as_uint(v)), "r"(mbar) : "memory");
}
__device__ __forceinline__ void mbar_init(uint32_t mbar, uint32_t count) {
    asm volatile("mbarrier.init.shared.b64 [%0], %1;" :: "r"(mbar), "r"(count) : "memory");
}
__device__ __forceinline__ void mbar_expect_tx(uint32_t mbar, uint32_t bytes) {
    asm volatile("mbarrier.arrive.expect_tx.shared.b64 _, [%0], %1;"
                 :: "r"(mbar), "r"(bytes) : "memory");
}
__device__ __forceinline__ void mbar_wait(uint32_t mbar, uint32_t parity) {
    uint32_t done;
    asm volatile(
        "{\n\t.reg .pred p;\n\t"
        "mbarrier.try_wait.parity.acquire.cluster.shared::cta.b64 p, [%1], %2;\n\t"
        "selp.b32 %0, 1, 0, p;\n\t}"
        : "=r"(done) : "r"(mbar), "r"(parity) : "memory");
    if (!done) {
        asm volatile(
            "{\n\t.reg .pred P1;\n\t"
            "WAIT_LOOP_%=:\n\t"
            "mbarrier.try_wait.parity.acquire.cluster.shared::cta.b64 P1, [%0], %1, 0x989680;\n\t"
            "@P1 bra.uni WAIT_DONE_%=;\n\t"
            "bra.uni WAIT_LOOP_%=;\n\t"
            "WAIT_DONE_%=:\n\t}"
            :: "r"(mbar), "r"(parity) : "memory");
    }
}

// =====================================================================
// Kernel 1: U = X @ W1x + b1.  Weights-in-registers + packed f32x2.
// Grid (2048, 4), 256 thr. Block tile: 64 rows x 128 cols, 8-row chunks.
// Thread (cp=tid&63, q=tid>>6): cols {2cp, 2cp+1}, ks [32q, 32q+32).
// =====================================================================
__global__ __launch_bounds__(256, 1) void precompute_u(
    const float* __restrict__ X, const float* __restrict__ W1,
    const float* __restrict__ b1)
{
    extern __shared__ float sm[];
    float* sX    = sm;              // 64 x 128   (32 KB)
    float* sPart = sm + 64 * DIN;   // 4 x 8 x 128 (16 KB)

    const int tid = threadIdx.x;
    const int rb  = blockIdx.x;     // 64-row block over B*T
    const int nb  = blockIdx.y;     // 128-col block over DHID
    const int cp  = tid & 63, q = tid >> 6;
    const int c0  = 2 * cp, k0 = 32 * q;

    // weights -> registers (packed over k)
    uint64_t w[2][16];
    #pragma unroll
    for (int kp = 0; kp < 16; ++kp)
        #pragma unroll
        for (int cc = 0; cc < 2; ++cc)
            w[cc][kp] = pack2(W1[(size_t)(k0 + 2*kp)     * DHID + nb*128 + c0 + cc],
                              W1[(size_t)(k0 + 2*kp + 1) * DHID + nb*128 + c0 + cc]);

    // X tile -> SMEM
    {
        const float4* Xg = (const float4*)(X + (size_t)rb * 64 * DIN);
        float4* sX4 = (float4*)sX;
        #pragma unroll
        for (int i = tid; i < 64 * DIN / 4; i += 256) sX4[i] = Xg[i];
    }
    // bias for my reduce lane (hoisted)
    const int rm = tid >> 5, rc4 = (tid & 31) * 4;
    const float4 bvr = *(const float4*)(b1 + nb * 128 + rc4);
    __syncthreads();

    for (int ch = 0; ch < 8; ++ch) {
        uint64_t acc[2][8];
        #pragma unroll
        for (int m = 0; m < 8; ++m) { acc[0][m] = 0ull; acc[1][m] = 0ull; }

        #pragma unroll
        for (int m = 0; m < 8; ++m) {
            const ulonglong2* ax = (const ulonglong2*)(sX + (ch*8 + m)*DIN + k0);
            uint64_t ar[16];
            #pragma unroll
            for (int i2 = 0; i2 < 8; ++i2) {
                ulonglong2 v = ax[i2];      // broadcast (q uniform per warp)
                ar[2*i2] = v.x; ar[2*i2+1] = v.y;
            }
            #pragma unroll
            for (int kp = 0; kp < 16; ++kp) {
                acc[0][m] = fma2(ar[kp], w[0][kp], acc[0][m]);
                acc[1][m] = fma2(ar[kp], w[1][kp], acc[1][m]);
            }
        }
        #pragma unroll
        for (int m = 0; m < 8; ++m) {
            float2 p = make_float2(hsum2(acc[0][m]), hsum2(acc[1][m]));
            *(float2*)&sPart[(q*8 + m)*128 + c0] = p;
        }
        __syncthreads();
        {   // reduce 4 k-quarters + bias, write 4 consecutive cols
            float4 v0 = *(float4*)&sPart[(0*8 + rm)*128 + rc4];
            float4 v1 = *(float4*)&sPart[(1*8 + rm)*128 + rc4];
            float4 v2 = *(float4*)&sPart[(2*8 + rm)*128 + rc4];
            float4 v3 = *(float4*)&sPart[(3*8 + rm)*128 + rc4];
            float4 o;
            o.x = v0.x + v1.x + v2.x + v3.x + bvr.x;
            o.y = v0.y + v1.y + v2.y + v3.y + bvr.y;
            o.z = v0.z + v1.z + v2.z + v3.z + bvr.z;
            o.w = v0.w + v1.w + v2.w + v3.w + bvr.w;
            int row = rb * 64 + ch * 8 + rm;     // linear b*T + t
            int b = row >> 9, t = row & (T_ - 1);
            *(float4*)(g_U + ((size_t)t * B_ + b) * DHID + nb*128 + rc4) = o;
        }
        __syncthreads();
    }
}

// =====================================================================
// Kernel 2: persistent recurrence. 32 clusters x 4 CTAs, 256 thr/CTA.
// CTA j: hidden cols [128j,128j+128), state quarter [32j,32j+32).
// Thread (cp, q): 2 cols x 32-k quarter of W1a and W2 in REGISTERS.
// SMEM: activations + partial buffer only. Comm protocol = R5 (proven).
// =====================================================================
__global__ __launch_bounds__(256, 1) __cluster_dims__(4, 1, 1)
void rnn_recur(const float* __restrict__ a0,
               const float* __restrict__ W1,
               const float* __restrict__ W2,
               const float* __restrict__ b2,
               float* __restrict__ out)
{
    extern __shared__ float sm[];
    // sm[0..3]: two mbarriers (16 B)
    float* sA    = sm + 4;                 // 8 x 128
    float* sH    = sA + MROWS * DST;       // 8 x 128
    float* sRed  = sH + MROWS * DST;       // 4 src x 8 x 32
    float* sB2   = sRed + 4 * MROWS * 32;  // 32
    float* sPart = sB2 + 32;               // 4 x 8 x 128

    const uint32_t mbRed = smem_u32(sm);
    const uint32_t mbA   = smem_u32(sm) + 8;

    const int j   = (int)cluster_rank();   // 0..3
    const int g   = blockIdx.x >> 2;       // batch-row group
    const int tid = threadIdx.x;
    const int cp  = tid & 63, q = tid >> 6;
    const int c0  = 2 * cp, k0 = 32 * q;

    // ---- weights -> registers (one time) ----
    uint64_t w1[2][16], w2[2][16];
    #pragma unroll
    for (int kp = 0; kp < 16; ++kp)
        #pragma unroll
        for (int cc = 0; cc < 2; ++cc) {
            w1[cc][kp] = pack2(
                W1[(size_t)(DIN + k0 + 2*kp)     * DHID + j*128 + c0 + cc],
                W1[(size_t)(DIN + k0 + 2*kp + 1) * DHID + j*128 + c0 + cc]);
            w2[cc][kp] = pack2(
                W2[(size_t)(j*128 + k0 + 2*kp)     * DST + c0 + cc],
                W2[(size_t)(j*128 + k0 + 2*kp + 1) * DST + c0 + cc]);
        }

    for (int i = tid; i < MROWS * DST; i += 256)
        sA[i] = a0[(size_t)g * MROWS * DST + i];
    if (tid < 32) sB2[tid] = b2[j * 32 + tid];
    if (tid == 0) { mbar_init(mbRed, 1); mbar_init(mbA, 1); }
    cluster_sync_all();

    // ---- fixed addresses ----
    // reduce/scatter items: m = (tid>>7) + 2r, c = tid&127
    const int rc = tid & 127, rmb = tid >> 7;
    const int oc = rc >> 5;                // owner CTA of my scatter column
    const uint32_t mbRedRem = mapa_shared(mbRed, (uint32_t)oc);
    uint32_t scat[4];
    {
        uint32_t base = mapa_shared(smem_u32(sRed), (uint32_t)oc);
        #pragma unroll
        for (int r = 0; r < 4; ++r)
            scat[r] = base + (uint32_t)(((j*MROWS + rmb + 2*r)*32 + (rc & 31)) * 4);
    }
    // owner reduce/broadcast: item (rm, rn)
    const int rm = tid >> 5, rn = tid & 31;
    uint32_t aRem[4], mbARem[4];
    #pragma unroll
    for (int c = 0; c < 4; ++c) {
        aRem[c]  = mapa_shared(smem_u32(sA), (uint32_t)c)
                 + (uint32_t)((rm * DST + j*32 + rn) * 4);
        mbARem[c] = mapa_shared(mbA, (uint32_t)c);
    }
    const size_t ubase0 = (size_t)(g * MROWS + rmb) * DHID + j*128 + rc;

    for (int t = 0; t < T_; ++t) {
        const uint32_t par = (uint32_t)(t & 1);
        if (tid == 0) { mbar_expect_tx(mbRed, 4096); mbar_expect_tx(mbA, 4096); }

        // U for this step (consumed after GEMM1; latency hidden)
        float uv[4];
        {
            const float* up = g_U + (size_t)t * B_ * DHID + ubase0;
            #pragma unroll
            for (int r = 0; r < 4; ++r) uv[r] = up[(size_t)(2*r) * DHID];
        }

        // ---- GEMM1: partials of a @ W1a (weights in regs) ----
        uint64_t acc[2][8];
        #pragma unroll
        for (int m = 0; m < 8; ++m) { acc[0][m] = 0ull; acc[1][m] = 0ull; }
        #pragma unroll
        for (int m = 0; m < 8; ++m) {
            const ulonglong2* ax = (const ulonglong2*)(sA + m*DST + k0);
            uint64_t ar[16];
            #pragma unroll
            for (int i2 = 0; i2 < 8; ++i2) {
                ulonglong2 v = ax[i2];     // warp broadcast
                ar[2*i2] = v.x; ar[2*i2+1] = v.y;
            }
            #pragma unroll
            for (int kp = 0; kp < 16; ++kp) {
                acc[0][m] = fma2(ar[kp], w1[0][kp], acc[0][m]);
                acc[1][m] = fma2(ar[kp], w1[1][kp], acc[1][m]);
            }
        }
        #pragma unroll
        for (int m = 0; m < 8; ++m) {
            float2 p = make_float2(hsum2(acc[0][m]), hsum2(acc[1][m]));
            *(float2*)&sPart[(q*8 + m)*128 + c0] = p;
        }
        __syncthreads();

        // ---- reduce k-quarters + U, tanh -> sH ----
        #pragma unroll
        for (int r = 0; r < 4; ++r) {
            int m = rmb + 2*r;
            float v = sPart[(0*8 + m)*128 + rc] + sPart[(1*8 + m)*128 + rc]
                    + sPart[(2*8 + m)*128 + rc] + sPart[(3*8 + m)*128 + rc]
                    + uv[r];
            sH[m*128 + rc] = fast_tanh(v);
        }
        __syncthreads();

        // ---- GEMM2: partials of h @ W2 (weights in regs) ----
        #pragma unroll
        for (int m = 0; m < 8; ++m) { acc[0][m] = 0ull; acc[1][m] = 0ull; }
        #pragma unroll
        for (int m = 0; m < 8; ++m) {
            const ulonglong2* hx = (const ulonglong2*)(sH + m*DST + k0);
            uint64_t hr[16];
            #pragma unroll
            for (int i2 = 0; i2 < 8; ++i2) {
                ulonglong2 v = hx[i2];     // warp broadcast
                hr[2*i2] = v.x; hr[2*i2+1] = v.y;
            }
            #pragma unroll
            for (int kp = 0; kp < 16; ++kp) {
                acc[0][m] = fma2(hr[kp], w2[0][kp], acc[0][m]);
                acc[1][m] = fma2(hr[kp], w2[1][kp], acc[1][m]);
            }
        }
        #pragma unroll
        for (int m = 0; m < 8; ++m) {
            float2 p = make_float2(hsum2(acc[0][m]), hsum2(acc[1][m]));
            *(float2*)&sPart[(q*8 + m)*128 + c0] = p;
        }
        __syncthreads();

        // ---- in-CTA reduce + scatter to owner CTA ----
        #pragma unroll
        for (int r = 0; r < 4; ++r) {
            int m = rmb + 2*r;
            float v = sPart[(0*8 + m)*128 + rc] + sPart[(1*8 + m)*128 + rc]
                    + sPart[(2*8 + m)*128 + rc] + sPart[(3*8 + m)*128 + rc];
            st_async_f32(scat[r], v, mbRedRem);
        }
        mbar_wait(mbRed, par);

        // ---- owner reduce + broadcast new a ----
        {
            float v = sA[rm * DST + j*32 + rn] + sB2[rn];
            #pragma unroll
            for (int c = 0; c < 4; ++c) v += sRed[(c*MROWS + rm)*32 + rn];
            #pragma unroll
            for (int c = 0; c < 4; ++c) st_async_f32(aRem[c], v, mbARem[c]);
        }
        mbar_wait(mbA, par);
        __syncthreads();
    }

    // ---- output ----
    out[(size_t)(g * MROWS + rm) * DST + j*32 + rn] = sA[rm * DST + j*32 + rn];
}

// =====================================================================
extern "C" void kernel_launch(void* const* d_in, const int* in_sizes, int n_in,
                              void* d_out, int out_size)
{
    const float* X  = (const float*)d_in[0];
    const float* a0 = (const float*)d_in[1];
    const float* W1 = (const float*)d_in[2];
    const float* b1 = (const float*)d_in[3];
    const float* W2 = (const float*)d_in[4];
    const float* b2 = (const float*)d_in[5];
    float* out = (float*)d_out;

    constexpr int PRE_SMEM = (64 * DIN + 4 * 8 * 128) * 4;                       // 48 KB
    constexpr int REC_SMEM = (4 + 2 * MROWS * DST + 4 * MROWS * 32 + 32
                              + 4 * 8 * 128) * 4;                                 // ~28.8 KB

    cudaFuncSetAttribute(precompute_u, cudaFuncAttributeMaxDynamicSharedMemorySize, PRE_SMEM);
    cudaFuncSetAttribute(rnn_recur,    cudaFuncAttributeMaxDynamicSharedMemorySize, REC_SMEM);

    precompute_u<<<dim3((B_ * T_) / 64, DHID / 128), 256, PRE_SMEM>>>(X, W1, b1);
    rnn_recur<<<(B_ / MROWS) * 4, 256, REC_SMEM>>>(a0, W1, W2, b2, out);
}